// round 1
// baseline (speedup 1.0000x reference)
#include <cuda_runtime.h>
#include <math.h>

#define NREL  500
#define BB    8192
#define KK    64
#define DIM   128
#define SPLIT 4
#define CAP   1024

__device__ __forceinline__ float warp_sum(float p) {
    p += __shfl_xor_sync(0xffffffffu, p, 16);
    p += __shfl_xor_sync(0xffffffffu, p, 8);
    p += __shfl_xor_sync(0xffffffffu, p, 4);
    p += __shfl_xor_sync(0xffffffffu, p, 2);
    p += __shfl_xor_sync(0xffffffffu, p, 1);
    return p;
}

__global__ void __launch_bounds__(256, 3) hybo_kernel(
    const int*   __restrict__ u_idx,
    const int*   __restrict__ r_idx,
    const int*   __restrict__ v_idx,
    const float* __restrict__ drug,      // [N_DRUGS, 128]
    const float* __restrict__ target,    // [N_TARGETS, 128]
    const float* __restrict__ relb,      // [NREL, 128]
    const float* __restrict__ relW,      // [NREL, 128, 128]
    const float* __restrict__ bias_h,
    const float* __restrict__ bias_t,
    float*       __restrict__ out)       // [B, K]
{
    extern __shared__ float Wsh[];                    // DIM*DIM floats = 64KB
    __shared__ __align__(16) float head[DIM];
    __shared__ __align__(16) float xv[DIM];
    __shared__ __align__(16) float mvec[DIM];         // mvec[0] = -time, mvec[1..] = nar
    __shared__ __align__(16) float rb[DIM];
    __shared__ int list[CAP];
    __shared__ int nmatch;

    const int r    = blockIdx.x;
    const int part = blockIdx.y;
    const int tid  = threadIdx.x;
    const int lane = tid & 31;
    const int warp = tid >> 5;

    if (tid == 0) nmatch = 0;

    // Stage W[r] into SMEM, fully coalesced float4 (16 per thread).
    {
        const float4* Wg  = (const float4*)(relW + (size_t)r * DIM * DIM);
        float4*       Ws4 = (float4*)Wsh;
        #pragma unroll
        for (int i = 0; i < 16; i++)
            Ws4[tid + 256 * i] = Wg[tid + 256 * i];
    }
    if (tid < DIM) rb[tid] = relb[r * DIM + tid];
    __syncthreads();

    // Scan this part's slice of r_idx: b = part + SPLIT*j.  Order in the
    // list doesn't matter — each b belongs to exactly one (r, part) cell.
    for (int j = tid; j < BB / SPLIT; j += 256) {
        int b = part + SPLIT * j;
        if (r_idx[b] == r) {
            int p = atomicAdd(&nmatch, 1);
            list[p] = b;
        }
    }
    __syncthreads();
    const int n = nmatch;

    for (int ii = 0; ii < n; ii++) {
        const int b = list[ii];
        const int u = u_idx[b];

        if (tid < DIM) head[tid] = drug[(size_t)u * DIM + tid];
        __syncthreads();

        const float4 hv = ((const float4*)head)[lane];

        // Phase 1: x[e] = dot(W[e,:], head).  Warp w covers e in [16w, 16w+16).
        #pragma unroll
        for (int i = 0; i < 16; i++) {
            int e = warp * 16 + i;
            const float4 wv = ((const float4*)(Wsh + e * DIM))[lane];
            float p = wv.x * hv.x + wv.y * hv.y + wv.z * hv.z + wv.w * hv.w;
            p = warp_sum(p);
            if (lane == 0) xv[e] = p;
        }
        __syncthreads();

        // Phase 2 (warp 0): time from raw x[0]; normalize nar = x[1:]+rb[1:].
        if (warp == 0) {
            const float x0   = xv[0];
            const float time = 2.5f / (1.0f + expf(-x0)) + 1.1f;
            const int d0 = lane * 4;
            float a0 = (d0 == 0) ? 0.0f : xv[d0] + rb[d0];
            float a1 = xv[d0 + 1] + rb[d0 + 1];
            float a2 = xv[d0 + 2] + rb[d0 + 2];
            float a3 = xv[d0 + 3] + rb[d0 + 3];
            float s = a0 * a0 + a1 * a1 + a2 * a2 + a3 * a3;
            s = warp_sum(s);                       // all lanes hold full sum
            const float scale = sqrtf((time * time - 1.0f) / s);
            mvec[d0]     = (d0 == 0) ? -time : a0 * scale;
            mvec[d0 + 1] = a1 * scale;
            mvec[d0 + 2] = a2 * scale;
            mvec[d0 + 3] = a3 * scale;
        }
        __syncthreads();

        const float4 mv  = ((const float4*)mvec)[lane];
        const float  bhv = bias_h[u];
        const int*   vb  = v_idx + b * KK;

        // Phase 3: warp w covers k in [8w, 8w+8).  512B coalesced row loads.
        #pragma unroll
        for (int i = 0; i < 8; i++) {
            int k = warp * 8 + i;
            int v = vb[k];
            const float4 tv = ((const float4*)(target + (size_t)v * DIM))[lane];
            float p = tv.x * mv.x + tv.y * mv.y + tv.z * mv.z + tv.w * mv.w;
            p = warp_sum(p);
            if (lane == 0)
                out[b * KK + k] = 8.0f + 2.0f * p + bhv + bias_t[v];
        }
        __syncthreads();   // protect head/xv/mvec before next iteration
    }
}

extern "C" void kernel_launch(void* const* d_in, const int* in_sizes, int n_in,
                              void* d_out, int out_size) {
    const int*   u_idx  = (const int*)  d_in[0];
    const int*   r_idx  = (const int*)  d_in[1];
    const int*   v_idx  = (const int*)  d_in[2];
    const float* drug   = (const float*)d_in[3];
    const float* target = (const float*)d_in[4];
    const float* relb   = (const float*)d_in[5];
    const float* relW   = (const float*)d_in[6];
    const float* bias_h = (const float*)d_in[7];
    const float* bias_t = (const float*)d_in[8];
    float*       out    = (float*)d_out;

    static bool attr_done = false;
    if (!attr_done) {
        cudaFuncSetAttribute(hybo_kernel,
                             cudaFuncAttributeMaxDynamicSharedMemorySize,
                             DIM * DIM * sizeof(float));
        attr_done = true;
    }

    dim3 grid(NREL, SPLIT);
    hybo_kernel<<<grid, 256, DIM * DIM * sizeof(float)>>>(
        u_idx, r_idx, v_idx, drug, target, relb, relW, bias_h, bias_t, out);
}

// round 2
// speedup vs baseline: 1.3654x; 1.3654x over previous
#include <cuda_runtime.h>
#include <math.h>

#define NREL  500
#define BB    8192
#define KK    64
#define DIM   128
#define SPLIT 4
#define CAP   512
#define WS    132   // W row stride in floats (pad 4 -> conflict-free LDS.128)

__device__ __forceinline__ float warp_sum(float p) {
    p += __shfl_xor_sync(0xffffffffu, p, 16);
    p += __shfl_xor_sync(0xffffffffu, p, 8);
    p += __shfl_xor_sync(0xffffffffu, p, 4);
    p += __shfl_xor_sync(0xffffffffu, p, 2);
    p += __shfl_xor_sync(0xffffffffu, p, 1);
    return p;
}

// Phase 2 + 3 for one item, entirely warp-local.
__device__ __forceinline__ void finish_item(
    int b, int u,
    float acc0, float acc1, float acc2, float acc3,   // x[e], e = lane+32m
    const float* __restrict__ rb,                      // smem [128]
    float*       __restrict__ mvw,                     // smem [128] scratch (per warp)
    const int*   __restrict__ v_idx,
    const float* __restrict__ target,
    const float* __restrict__ bias_h,
    const float* __restrict__ bias_t,
    float*       __restrict__ out,
    int lane)
{
    // time from RAW x[0] (before rb), per reference.
    const float x0   = __shfl_sync(0xffffffffu, acc0, 0);
    const float time = 2.5f / (1.0f + expf(-x0)) + 1.1f;

    float a0 = acc0 + rb[lane];
    float a1 = acc1 + rb[lane + 32];
    float a2 = acc2 + rb[lane + 64];
    float a3 = acc3 + rb[lane + 96];
    float s  = ((lane == 0) ? 0.0f : a0 * a0) + a1 * a1 + a2 * a2 + a3 * a3;
    s = warp_sum(s);
    const float scale = sqrtf((time * time - 1.0f) / s);

    __syncwarp();
    mvw[lane]      = (lane == 0) ? -time : a0 * scale;
    mvw[lane + 32] = a1 * scale;
    mvw[lane + 64] = a2 * scale;
    mvw[lane + 96] = a3 * scale;
    __syncwarp();
    const float4 m4 = *(const float4*)(mvw + 4 * lane);

    const int   v0  = v_idx[b * KK + lane];
    const int   v1  = v_idx[b * KK + 32 + lane];
    const float bh  = bias_h[u];
    const float bt0 = bias_t[v0];
    const float bt1 = bias_t[v1];

    float res0 = 0.0f, res1 = 0.0f;
    #pragma unroll 4
    for (int k = 0; k < 32; k++) {
        int vk = __shfl_sync(0xffffffffu, v0, k);
        const float4 t4 = *(const float4*)(target + (size_t)vk * DIM + 4 * lane);
        float p = t4.x * m4.x + t4.y * m4.y + t4.z * m4.z + t4.w * m4.w;
        p = warp_sum(p);
        if (lane == k) res0 = p;
    }
    #pragma unroll 4
    for (int k = 0; k < 32; k++) {
        int vk = __shfl_sync(0xffffffffu, v1, k);
        const float4 t4 = *(const float4*)(target + (size_t)vk * DIM + 4 * lane);
        float p = t4.x * m4.x + t4.y * m4.y + t4.z * m4.z + t4.w * m4.w;
        p = warp_sum(p);
        if (lane == k) res1 = p;
    }
    out[b * KK + lane]      = 8.0f + 2.0f * res0 + bh + bt0;
    out[b * KK + 32 + lane] = 8.0f + 2.0f * res1 + bh + bt1;
}

__global__ void __launch_bounds__(256, 3) hybo_kernel(
    const int*   __restrict__ u_idx,
    const int*   __restrict__ r_idx,
    const int*   __restrict__ v_idx,
    const float* __restrict__ drug,
    const float* __restrict__ target,
    const float* __restrict__ relb,
    const float* __restrict__ relW,
    const float* __restrict__ bias_h,
    const float* __restrict__ bias_t,
    float*       __restrict__ out)
{
    extern __shared__ float Wsh[];                 // [128][WS] floats
    __shared__ float rb[DIM];
    __shared__ __align__(16) float mv[8][DIM];     // per-warp mvec scratch
    __shared__ int  list[CAP];
    __shared__ int  nmatch;

    const int r    = blockIdx.x;
    const int part = blockIdx.y;
    const int tid  = threadIdx.x;
    const int lane = tid & 31;
    const int warp = tid >> 5;

    if (tid == 0) nmatch = 0;

    // Stage W[r] row-major with stride WS. Global reads coalesced (4B/lane),
    // STS banks = (4e + d) % 32 with d consecutive per warp -> conflict-free.
    {
        const float* Wg = relW + (size_t)r * DIM * DIM;
        #pragma unroll
        for (int i = tid; i < DIM * DIM; i += 256) {
            int e = i >> 7, d = i & 127;
            Wsh[e * WS + d] = Wg[i];
        }
    }
    if (tid < DIM) rb[tid] = relb[r * DIM + tid];
    __syncthreads();

    // Scan this part's slice: b = part + SPLIT*j.
    for (int j = tid; j < BB / SPLIT; j += 256) {
        int b = part + SPLIT * j;
        if (r_idx[b] == r) {
            int p = atomicAdd(&nmatch, 1);
            if (p < CAP) list[p] = b;
        }
    }
    __syncthreads();
    const int n = nmatch;

    // Per-warp independent items, two at a time sharing each W read.
    const float4* w0 = (const float4*)(Wsh + (lane      ) * WS);
    const float4* w1 = (const float4*)(Wsh + (lane + 32 ) * WS);
    const float4* w2 = (const float4*)(Wsh + (lane + 64 ) * WS);
    const float4* w3 = (const float4*)(Wsh + (lane + 96 ) * WS);

    for (int base = 2 * warp; base < n; base += 16) {
        const int  b0  = list[base];
        const bool two = (base + 1 < n);
        const int  b1  = two ? list[base + 1] : b0;
        const int  u0  = u_idx[b0];
        const int  u1  = u_idx[b1];

        const float4 hA = *(const float4*)(drug + (size_t)u0 * DIM + 4 * lane);
        const float4 hB = *(const float4*)(drug + (size_t)u1 * DIM + 4 * lane);

        float A0 = 0.f, A1 = 0.f, A2 = 0.f, A3 = 0.f;
        float B0 = 0.f, B1 = 0.f, B2 = 0.f, B3 = 0.f;

        #pragma unroll 4
        for (int d4 = 0; d4 < 32; d4++) {
            const float ax = __shfl_sync(0xffffffffu, hA.x, d4);
            const float ay = __shfl_sync(0xffffffffu, hA.y, d4);
            const float az = __shfl_sync(0xffffffffu, hA.z, d4);
            const float aw = __shfl_sync(0xffffffffu, hA.w, d4);
            const float bx = __shfl_sync(0xffffffffu, hB.x, d4);
            const float by = __shfl_sync(0xffffffffu, hB.y, d4);
            const float bz = __shfl_sync(0xffffffffu, hB.z, d4);
            const float bw = __shfl_sync(0xffffffffu, hB.w, d4);

            const float4 W0 = w0[d4];
            const float4 W1 = w1[d4];
            const float4 W2 = w2[d4];
            const float4 W3 = w3[d4];

            A0 = fmaf(ax, W0.x, A0); A0 = fmaf(ay, W0.y, A0);
            A0 = fmaf(az, W0.z, A0); A0 = fmaf(aw, W0.w, A0);
            A1 = fmaf(ax, W1.x, A1); A1 = fmaf(ay, W1.y, A1);
            A1 = fmaf(az, W1.z, A1); A1 = fmaf(aw, W1.w, A1);
            A2 = fmaf(ax, W2.x, A2); A2 = fmaf(ay, W2.y, A2);
            A2 = fmaf(az, W2.z, A2); A2 = fmaf(aw, W2.w, A2);
            A3 = fmaf(ax, W3.x, A3); A3 = fmaf(ay, W3.y, A3);
            A3 = fmaf(az, W3.z, A3); A3 = fmaf(aw, W3.w, A3);

            B0 = fmaf(bx, W0.x, B0); B0 = fmaf(by, W0.y, B0);
            B0 = fmaf(bz, W0.z, B0); B0 = fmaf(bw, W0.w, B0);
            B1 = fmaf(bx, W1.x, B1); B1 = fmaf(by, W1.y, B1);
            B1 = fmaf(bz, W1.z, B1); B1 = fmaf(bw, W1.w, B1);
            B2 = fmaf(bx, W2.x, B2); B2 = fmaf(by, W2.y, B2);
            B2 = fmaf(bz, W2.z, B2); B2 = fmaf(bw, W2.w, B2);
            B3 = fmaf(bx, W3.x, B3); B3 = fmaf(by, W3.y, B3);
            B3 = fmaf(bz, W3.z, B3); B3 = fmaf(bw, W3.w, B3);
        }

        finish_item(b0, u0, A0, A1, A2, A3, rb, mv[warp],
                    v_idx, target, bias_h, bias_t, out, lane);
        if (two)
            finish_item(b1, u1, B0, B1, B2, B3, rb, mv[warp],
                        v_idx, target, bias_h, bias_t, out, lane);
    }
}

extern "C" void kernel_launch(void* const* d_in, const int* in_sizes, int n_in,
                              void* d_out, int out_size) {
    const int*   u_idx  = (const int*)  d_in[0];
    const int*   r_idx  = (const int*)  d_in[1];
    const int*   v_idx  = (const int*)  d_in[2];
    const float* drug   = (const float*)d_in[3];
    const float* target = (const float*)d_in[4];
    const float* relb   = (const float*)d_in[5];
    const float* relW   = (const float*)d_in[6];
    const float* bias_h = (const float*)d_in[7];
    const float* bias_t = (const float*)d_in[8];
    float*       out    = (float*)d_out;

    static bool attr_done = false;
    if (!attr_done) {
        cudaFuncSetAttribute(hybo_kernel,
                             cudaFuncAttributeMaxDynamicSharedMemorySize,
                             DIM * WS * sizeof(float));
        attr_done = true;
    }

    dim3 grid(NREL, SPLIT);
    hybo_kernel<<<grid, 256, DIM * WS * sizeof(float)>>>(
        u_idx, r_idx, v_idx, drug, target, relb, relW, bias_h, bias_t, out);
}